// round 1
// baseline (speedup 1.0000x reference)
#include <cuda_runtime.h>

// Gammatone filterbank: 4 cascaded complex one-pole IIRs.
// B=8, T=32000, C=128. Output [B, T, C] fp32 (real part of stage-4 state).
//
// Chunk-parallel over time with warm-up halo: |coef| <= ~0.963, so starting
// from zero state H=576 samples early gives truncation error ~1e-6 relative.

#define TT 32000
#define CC 128
#define BB 8
#define LL 500              // output samples per chunk
#define HH 576              // warm-up halo
#define KK (TT / LL)        // 64 chunks

__device__ __forceinline__ void stage(float cr, float ci,
                                      float& sr, float& si,
                                      float xr, float xi) {
    // s' = coef * s + x  (complex)
    float nr = fmaf(cr, sr, xr);
    nr = fmaf(-ci, si, nr);
    float ni = fmaf(cr, si, xi);
    ni = fmaf(ci, sr, ni);
    sr = nr;
    si = ni;
}

__global__ __launch_bounds__(CC, 8)
void gammatone_kernel(const float* __restrict__ inp,
                      const float* __restrict__ coef_re,
                      const float* __restrict__ coef_im,
                      const float* __restrict__ factor,
                      float* __restrict__ out)
{
    __shared__ float xs[HH + LL];

    const int chunk = blockIdx.x;       // 0..KK-1
    const int b     = blockIdx.y;       // 0..BB-1
    const int c     = threadIdx.x;      // 0..CC-1

    const int t0    = chunk * LL;
    int start = t0 - HH;
    if (start < 0) start = 0;
    const int nwarm = t0 - start;
    const int total = nwarm + LL;

    // Stage the input window into shared memory (broadcast reads later).
    const float* ib = inp + b * TT + start;
    for (int i = c; i < total; i += CC)
        xs[i] = ib[i];
    __syncthreads();

    const float cr = coef_re[c];
    const float ci = coef_im[c];
    const float f  = factor[c];

    float s1r = 0.f, s1i = 0.f, s2r = 0.f, s2i = 0.f;
    float s3r = 0.f, s3i = 0.f, s4r = 0.f, s4i = 0.f;

    // Warm-up: run the cascade without emitting output.
    #pragma unroll 4
    for (int i = 0; i < nwarm; ++i) {
        float x = xs[i] * f;
        stage(cr, ci, s1r, s1i, x,   0.f);
        stage(cr, ci, s2r, s2i, s1r, s1i);
        stage(cr, ci, s3r, s3i, s2r, s2i);
        stage(cr, ci, s4r, s4i, s3r, s3i);
    }

    // Emit: out[b, t0 + i, c] = Re(stage4)
    float* op = out + ((size_t)(b * TT + t0)) * CC + c;
    #pragma unroll 4
    for (int i = 0; i < LL; ++i) {
        float x = xs[nwarm + i] * f;
        stage(cr, ci, s1r, s1i, x,   0.f);
        stage(cr, ci, s2r, s2i, s1r, s1i);
        stage(cr, ci, s3r, s3i, s2r, s2i);
        stage(cr, ci, s4r, s4i, s3r, s3i);
        op[(size_t)i * CC] = s4r;
    }
}

extern "C" void kernel_launch(void* const* d_in, const int* in_sizes, int n_in,
                              void* d_out, int out_size)
{
    const float* inp     = (const float*)d_in[0];
    const float* coef_re = (const float*)d_in[1];
    const float* coef_im = (const float*)d_in[2];
    const float* factor  = (const float*)d_in[3];
    float* out = (float*)d_out;

    dim3 grid(KK, BB);
    gammatone_kernel<<<grid, CC>>>(inp, coef_re, coef_im, factor, out);
}

// round 5
// speedup vs baseline: 1.2358x; 1.2358x over previous
#include <cuda_runtime.h>

// Gammatone filterbank: 4 cascaded complex one-pole IIRs.
// B=8, T=32000, C=128. Output [B, T, C] fp32.
//
// Round 2: packed f32x2 math (2 channels/thread), per-warp adaptive warm-up
// halo, factor applied at emit (cascade is linear).

#define TT 32000
#define CC 128
#define BB 8
#define LL 320
#define KK (TT / LL)        // 100 chunks
#define HMAXC 768           // clamp on warm-up halo
#define NTHR 64             // 64 threads -> 128 channels (2/thread)

typedef unsigned long long u64;

__device__ __forceinline__ u64 pack2(float lo, float hi) {
    u64 r; asm("mov.b64 %0, {%1, %2};" : "=l"(r) : "f"(lo), "f"(hi)); return r;
}
__device__ __forceinline__ u64 fma2(u64 a, u64 b, u64 c) {
    u64 d; asm("fma.rn.f32x2 %0, %1, %2, %3;" : "=l"(d) : "l"(a), "l"(b), "l"(c)); return d;
}
__device__ __forceinline__ u64 mul2(u64 a, u64 b) {
    u64 d; asm("mul.rn.f32x2 %0, %1, %2;" : "=l"(d) : "l"(a), "l"(b)); return d;
}

// One complex one-pole stage for a packed channel pair:
//   s' = coef * s + x   (complex, lane-wise over 2 channels)
#define STAGE(sr, si, xr, xi) do {              \
    u64 _nr = fma2(cr2, sr, xr);                \
    _nr = fma2(cin2, si, _nr);                  \
    u64 _ni = fma2(cr2, si, xi);                \
    _ni = fma2(ci2, sr, _ni);                   \
    sr = _nr; si = _ni; } while (0)

__global__ __launch_bounds__(NTHR)
void gammatone_kernel(const float* __restrict__ inp,
                      const float* __restrict__ coef_re,
                      const float* __restrict__ coef_im,
                      const float* __restrict__ factor,
                      float* __restrict__ out)
{
    __shared__ float2 xs[HMAXC + LL];

    const int chunk = blockIdx.x;     // 0..KK-1
    const int b     = blockIdx.y;     // 0..BB-1
    const int j     = threadIdx.x;    // 0..63 -> channels 2j, 2j+1

    const int t0 = chunk * LL;
    const int W  = min(t0, HMAXC);    // staged halo window
    const int total = W + LL;

    // Stage input window as duplicated float2 so one LDS.64 gives (x, x).
    const float* ib = inp + b * TT + (t0 - W);
    for (int i = j; i < total; i += NTHR) {
        float v = ib[i];
        xs[i] = make_float2(v, v);
    }
    __syncthreads();

    const float2 crv = ((const float2*)coef_re)[j];
    const float2 civ = ((const float2*)coef_im)[j];
    const float2 fv  = ((const float2*)factor)[j];
    const u64 cr2  = pack2(crv.x,  crv.y);
    const u64 ci2  = pack2(civ.x,  civ.y);
    const u64 cin2 = pack2(-civ.x, -civ.y);
    const u64 f2   = pack2(fv.x,   fv.y);

    // Per-warp adaptive warm-up: halo ~ 11.5 / (-ln|coef|) + slack.
    float r0 = sqrtf(crv.x * crv.x + civ.x * civ.x);
    float r1 = sqrtf(crv.y * crv.y + civ.y * civ.y);
    float rmax = fminf(fmaxf(r0, r1), 0.9999f);
    int H = (int)ceilf(11.5f / (-__logf(rmax))) + 64;
    H = min(H, HMAXC);
    H = (int)__reduce_max_sync(0xffffffffu, (unsigned)H);
    const int nw = min(H, W);

    u64 s1r = 0, s1i = 0, s2r = 0, s2i = 0;
    u64 s3r = 0, s3i = 0, s4r = 0, s4i = 0;

    const u64* xp = (const u64*)(xs + (W - nw));  // warm-up window start
    const u64 z = 0;

    // Warm-up: cascade on raw x (factor folded out; filter is linear).
    #pragma unroll 4
    for (int i = 0; i < nw; ++i) {
        u64 x = xp[i];
        STAGE(s1r, s1i, x,   z);
        STAGE(s2r, s2i, s1r, s1i);
        STAGE(s3r, s3i, s2r, s2i);
        STAGE(s4r, s4i, s3r, s3i);
    }

    // Emit: out[b, t0+i, {2j,2j+1}] = factor * Re(stage4)   (one STG.64)
    const u64* xe = (const u64*)(xs + W);
    u64* op = (u64*)(out + ((size_t)(b * TT + t0)) * CC) + j;
    #pragma unroll 4
    for (int i = 0; i < LL; ++i) {
        u64 x = xe[i];
        STAGE(s1r, s1i, x,   z);
        STAGE(s2r, s2i, s1r, s1i);
        STAGE(s3r, s3i, s2r, s2i);
        STAGE(s4r, s4i, s3r, s3i);
        op[(size_t)i * (CC / 2)] = mul2(s4r, f2);
    }
}

extern "C" void kernel_launch(void* const* d_in, const int* in_sizes, int n_in,
                              void* d_out, int out_size)
{
    const float* inp     = (const float*)d_in[0];
    const float* coef_re = (const float*)d_in[1];
    const float* coef_im = (const float*)d_in[2];
    const float* factor  = (const float*)d_in[3];
    float* out = (float*)d_out;

    dim3 grid(KK, BB);
    gammatone_kernel<<<grid, NTHR>>>(inp, coef_re, coef_im, factor, out);
}